// round 11
// baseline (speedup 1.0000x reference)
#include <cuda_runtime.h>
#include <math.h>
#include <stdint.h>

#define TOTAL  2048
#define HIDDEN 1024
#define NHEAD  16
#define DH     64
#define NSEG   8
#define NCU    9
#define LOG2E  1.4426950408889634f

// Scratch (static device arrays — no allocation inside kernel_launch).
__device__ __align__(256) float g_q[TOTAL * HIDDEN];
__device__ __align__(256) float g_k[TOTAL * HIDDEN];
__device__ __align__(256) float g_v[TOTAL * HIDDEN];
__device__ __align__(256) float g_ctx[TOTAL * HIDDEN];
// tf32-rounded copies of inputs (rounded once per launch, outside GEMM hot loop)
__device__ __align__(256) float g_xt[TOTAL * HIDDEN];
__device__ __align__(256) float g_wq[HIDDEN * HIDDEN];
__device__ __align__(256) float g_wk[HIDDEN * HIDDEN];
__device__ __align__(256) float g_wv[HIDDEN * HIDDEN];
__device__ __align__(256) float g_wo[HIDDEN * HIDDEN];

__device__ __forceinline__ int segid_of(const int* scu, int t) {
    int s = 0;
    #pragma unroll
    for (int i = 0; i < NSEG - 1; i++) {
        if (scu[s + 1] <= t) s++;
    }
    return s;
}

__device__ __forceinline__ uint32_t f2tf32(float f) {
    uint32_t u;
    asm("cvt.rna.tf32.f32 %0, %1;" : "=r"(u) : "f"(f));
    return u;
}

__device__ __forceinline__ void mma_tf32(
    float& d0, float& d1, float& d2, float& d3,
    uint32_t a0, uint32_t a1, uint32_t a2, uint32_t a3,
    uint32_t b0, uint32_t b1)
{
    asm volatile(
        "mma.sync.aligned.m16n8k8.row.col.f32.tf32.tf32.f32 "
        "{%0,%1,%2,%3}, {%4,%5,%6,%7}, {%8,%9}, {%0,%1,%2,%3};"
        : "+f"(d0), "+f"(d1), "+f"(d2), "+f"(d3)
        : "r"(a0), "r"(a1), "r"(a2), "r"(a3), "r"(b0), "r"(b1));
}

__device__ __forceinline__ void cp16(void* smem, const void* g) {
    uint32_t s = (uint32_t)__cvta_generic_to_shared(smem);
    asm volatile("cp.async.ca.shared.global [%0], [%1], 16;" :: "r"(s), "l"(g));
}
__device__ __forceinline__ void cp_commit() {
    asm volatile("cp.async.commit_group;");
}
__device__ __forceinline__ void cp_wait0() {
    asm volatile("cp.async.wait_group 0;");
}

// ---------------------------------------------------------------------------
// Round 5 tensors to tf32 (kept in fp32 storage). z selects the tensor.
// ---------------------------------------------------------------------------
__global__ void __launch_bounds__(256) round_tf32_kernel(
    const float* __restrict__ x,
    const float* __restrict__ wq, const float* __restrict__ wk,
    const float* __restrict__ wv, const float* __restrict__ wo,
    float* __restrict__ xt,
    float* __restrict__ tq, float* __restrict__ tk,
    float* __restrict__ tv, float* __restrict__ to)
{
    const float* src; float* dst; int n;
    switch (blockIdx.z) {
        case 0:  src = x;  dst = xt; n = TOTAL * HIDDEN;  break;
        case 1:  src = wq; dst = tq; n = HIDDEN * HIDDEN; break;
        case 2:  src = wk; dst = tk; n = HIDDEN * HIDDEN; break;
        case 3:  src = wv; dst = tv; n = HIDDEN * HIDDEN; break;
        default: src = wo; dst = to; n = HIDDEN * HIDDEN; break;
    }
    int idx = (blockIdx.x * 256 + threadIdx.x) * 4;
    if (idx < n) {
        float4 t = *(const float4*)(src + idx);
        float4 s;
        s.x = __uint_as_float(f2tf32(t.x));
        s.y = __uint_as_float(f2tf32(t.y));
        s.z = __uint_as_float(f2tf32(t.z));
        s.w = __uint_as_float(f2tf32(t.w));
        *(float4*)(dst + idx) = s;
    }
}

// ---------------------------------------------------------------------------
// Triple-GEMM: C_z[M,N] = A[M,K] @ W_z[N,K]^T + b_z[N], z = blockIdx.z.
// Inputs MUST already be tf32-rounded (no cvt in the hot loop).
// 128x128 tile, BK=16, 256 threads, cp.async 2-stage double buffering.
// ---------------------------------------------------------------------------
__global__ void __launch_bounds__(256) gemm3_tf32_nt_bias(
    const float* __restrict__ A,
    const float* __restrict__ W0, const float* __restrict__ b0, float* __restrict__ C0,
    const float* __restrict__ W1, const float* __restrict__ b1, float* __restrict__ C1,
    const float* __restrict__ W2, const float* __restrict__ b2, float* __restrict__ C2,
    int M, int N, int K)
{
    const float* B; const float* bias; float* C;
    if (blockIdx.z == 0)      { B = W0; bias = b0; C = C0; }
    else if (blockIdx.z == 1) { B = W1; bias = b1; C = C1; }
    else                      { B = W2; bias = b2; C = C2; }

    __shared__ __align__(16) float As[2][128][20];
    __shared__ __align__(16) float Bs[2][128][20];

    const int tid  = threadIdx.x;
    const int lane = tid & 31;
    const int wid  = tid >> 5;
    const int wm   = (wid & 1) * 64;
    const int wn   = (wid >> 1) * 32;
    const int row0 = blockIdx.y * 128;
    const int col0 = blockIdx.x * 128;

    const int g  = lane >> 2;
    const int t4 = lane & 3;

    float acc[4][4][4];
    #pragma unroll
    for (int i = 0; i < 4; i++)
        #pragma unroll
        for (int j = 0; j < 4; j++)
            #pragma unroll
            for (int f = 0; f < 4; f++) acc[i][j][f] = 0.f;

    const int lr = tid >> 1;          // 0..127
    const int lc = (tid & 1) * 8;     // 0 or 8

    const float* Arow = A + (size_t)(row0 + lr) * K + lc;
    const float* Brow = B + (size_t)(col0 + lr) * K + lc;

    cp16(&As[0][lr][lc],     Arow);
    cp16(&As[0][lr][lc + 4], Arow + 4);
    cp16(&Bs[0][lr][lc],     Brow);
    cp16(&Bs[0][lr][lc + 4], Brow + 4);
    cp_commit();

    for (int k0 = 0; k0 < K; k0 += 16) {
        const int st = (k0 >> 4) & 1;
        cp_wait0();
        __syncthreads();

        if (k0 + 16 < K) {
            const float* An = Arow + k0 + 16;
            const float* Bn = Brow + k0 + 16;
            cp16(&As[st ^ 1][lr][lc],     An);
            cp16(&As[st ^ 1][lr][lc + 4], An + 4);
            cp16(&Bs[st ^ 1][lr][lc],     Bn);
            cp16(&Bs[st ^ 1][lr][lc + 4], Bn + 4);
            cp_commit();
        }

        #pragma unroll
        for (int kk = 0; kk < 16; kk += 8) {
            uint32_t af[4][4];
            #pragma unroll
            for (int mi = 0; mi < 4; mi++) {
                int r = wm + mi * 16;
                af[mi][0] = __float_as_uint(As[st][r + g     ][kk + t4    ]);
                af[mi][1] = __float_as_uint(As[st][r + g + 8 ][kk + t4    ]);
                af[mi][2] = __float_as_uint(As[st][r + g     ][kk + t4 + 4]);
                af[mi][3] = __float_as_uint(As[st][r + g + 8 ][kk + t4 + 4]);
            }
            uint32_t bf[4][2];
            #pragma unroll
            for (int ni = 0; ni < 4; ni++) {
                int n = wn + ni * 8;
                bf[ni][0] = __float_as_uint(Bs[st][n + g][kk + t4    ]);
                bf[ni][1] = __float_as_uint(Bs[st][n + g][kk + t4 + 4]);
            }
            #pragma unroll
            for (int mi = 0; mi < 4; mi++)
                #pragma unroll
                for (int ni = 0; ni < 4; ni++)
                    mma_tf32(acc[mi][ni][0], acc[mi][ni][1], acc[mi][ni][2], acc[mi][ni][3],
                             af[mi][0], af[mi][1], af[mi][2], af[mi][3],
                             bf[ni][0], bf[ni][1]);
        }
    }

    #pragma unroll
    for (int ni = 0; ni < 4; ni++) {
        int c = col0 + wn + ni * 8 + 2 * t4;
        float2 bv = *(const float2*)(bias + c);
        #pragma unroll
        for (int mi = 0; mi < 4; mi++) {
            int r = row0 + wm + mi * 16 + g;
            float2 v0 = make_float2(acc[mi][ni][0] + bv.x, acc[mi][ni][1] + bv.y);
            float2 v1 = make_float2(acc[mi][ni][2] + bv.x, acc[mi][ni][3] + bv.y);
            *(float2*)(C + (size_t)r * N + c)       = v0;
            *(float2*)(C + (size_t)(r + 8) * N + c) = v1;
        }
    }
}

// ---------------------------------------------------------------------------
// Fused flash attention with block-diagonal (segment) masking.
// Grid: (TOTAL/64, NHEAD). 128 threads = 4 warps; warp w owns q rows
// [q0+16w, q0+16w+16). Online softmax, tf32 mma for QK^T and PV.
// ctx is written tf32-rounded so the O-projection needs no conversion.
// ---------------------------------------------------------------------------
__global__ void __launch_bounds__(128) flash_attn_kernel(
    const float* __restrict__ q, const float* __restrict__ k,
    const float* __restrict__ v, const int* __restrict__ cu,
    float* __restrict__ ctx)
{
    const int h  = blockIdx.y;
    const int q0 = blockIdx.x * 64;

    __shared__ __align__(16) int   scu[NCU];
    __shared__ __align__(16) int   ksegS[64];
    __shared__ __align__(16) float Ks[64][68];   // K tile, later aliased as P tile
    __shared__ __align__(16) float Vs[64][68];   // V tile, [k][d] natural

    const int tid  = threadIdx.x;
    const int lane = tid & 31;
    const int w    = tid >> 5;
    const int wm   = w * 16;
    const int g    = lane >> 2;
    const int t4   = lane & 3;

    if (tid < NCU) scu[tid] = cu[tid];
    __syncthreads();

    {
        const int r0 = tid >> 4;
        const int c4 = (tid & 15) * 4;
        #pragma unroll
        for (int i = 0; i < 8; i++) {
            int r = r0 + i * 8;
            float4 t = *(const float4*)(q + (size_t)(q0 + r) * HIDDEN + h * DH + c4);
            float4 s;
            s.x = __uint_as_float(f2tf32(t.x * 0.125f));
            s.y = __uint_as_float(f2tf32(t.y * 0.125f));
            s.z = __uint_as_float(f2tf32(t.z * 0.125f));
            s.w = __uint_as_float(f2tf32(t.w * 0.125f));
            *(float4*)&Ks[r][c4] = s;
        }
    }
    __syncthreads();

    uint32_t qf[8][4];
    #pragma unroll
    for (int kk = 0; kk < 8; kk++) {
        qf[kk][0] = __float_as_uint(Ks[wm + g     ][kk * 8 + t4    ]);
        qf[kk][1] = __float_as_uint(Ks[wm + g + 8 ][kk * 8 + t4    ]);
        qf[kk][2] = __float_as_uint(Ks[wm + g     ][kk * 8 + t4 + 4]);
        qf[kk][3] = __float_as_uint(Ks[wm + g + 8 ][kk * 8 + t4 + 4]);
    }

    const int qs0 = segid_of(scu, q0 + wm + g);
    const int qs1 = segid_of(scu, q0 + wm + g + 8);
    const int s_lo = segid_of(scu, q0);
    const int s_hi = segid_of(scu, q0 + 63);
    const int ustart = scu[s_lo];
    const int uend   = scu[s_hi + 1];

    float m0 = -1e30f, m1 = -1e30f, l0 = 0.f, l1 = 0.f;
    float of[8][4];
    #pragma unroll
    for (int ni = 0; ni < 8; ni++)
        #pragma unroll
        for (int f = 0; f < 4; f++) of[ni][f] = 0.f;

    __syncthreads();

    for (int kb = (ustart / 64) * 64; kb < uend; kb += 64) {
        {
            const int r0 = tid >> 4;
            const int c4 = (tid & 15) * 4;
            #pragma unroll
            for (int i = 0; i < 8; i++) {
                int r = r0 + i * 8;
                float4 tk = *(const float4*)(k + (size_t)(kb + r) * HIDDEN + h * DH + c4);
                float4 tv = *(const float4*)(v + (size_t)(kb + r) * HIDDEN + h * DH + c4);
                float4 s;
                s.x = __uint_as_float(f2tf32(tk.x)); s.y = __uint_as_float(f2tf32(tk.y));
                s.z = __uint_as_float(f2tf32(tk.z)); s.w = __uint_as_float(f2tf32(tk.w));
                *(float4*)&Ks[r][c4] = s;
                s.x = __uint_as_float(f2tf32(tv.x)); s.y = __uint_as_float(f2tf32(tv.y));
                s.z = __uint_as_float(f2tf32(tv.z)); s.w = __uint_as_float(f2tf32(tv.w));
                *(float4*)&Vs[r][c4] = s;
            }
            if (tid < 64) ksegS[tid] = segid_of(scu, kb + tid);
        }
        __syncthreads();

        float sf[8][4];
        #pragma unroll
        for (int ni = 0; ni < 8; ni++)
            #pragma unroll
            for (int f = 0; f < 4; f++) sf[ni][f] = 0.f;

        #pragma unroll
        for (int kk = 0; kk < 8; kk++) {
            #pragma unroll
            for (int ni = 0; ni < 8; ni++) {
                uint32_t b0 = __float_as_uint(Ks[ni * 8 + g][kk * 8 + t4    ]);
                uint32_t b1 = __float_as_uint(Ks[ni * 8 + g][kk * 8 + t4 + 4]);
                mma_tf32(sf[ni][0], sf[ni][1], sf[ni][2], sf[ni][3],
                         qf[kk][0], qf[kk][1], qf[kk][2], qf[kk][3], b0, b1);
            }
        }

        float rmax0 = -1e30f, rmax1 = -1e30f;
        #pragma unroll
        for (int ni = 0; ni < 8; ni++) {
            int col = ni * 8 + 2 * t4;
            int ks0 = ksegS[col], ks1 = ksegS[col + 1];
            sf[ni][0] = (ks0 == qs0) ? sf[ni][0] : -1e30f;
            sf[ni][1] = (ks1 == qs0) ? sf[ni][1] : -1e30f;
            sf[ni][2] = (ks0 == qs1) ? sf[ni][2] : -1e30f;
            sf[ni][3] = (ks1 == qs1) ? sf[ni][3] : -1e30f;
            rmax0 = fmaxf(rmax0, fmaxf(sf[ni][0], sf[ni][1]));
            rmax1 = fmaxf(rmax1, fmaxf(sf[ni][2], sf[ni][3]));
        }
        rmax0 = fmaxf(rmax0, __shfl_xor_sync(0xffffffffu, rmax0, 1));
        rmax0 = fmaxf(rmax0, __shfl_xor_sync(0xffffffffu, rmax0, 2));
        rmax1 = fmaxf(rmax1, __shfl_xor_sync(0xffffffffu, rmax1, 1));
        rmax1 = fmaxf(rmax1, __shfl_xor_sync(0xffffffffu, rmax1, 2));

        float mn0 = fmaxf(m0, rmax0);
        float mn1 = fmaxf(m1, rmax1);
        float a0 = exp2f((m0 - mn0) * LOG2E);
        float a1 = exp2f((m1 - mn1) * LOG2E);

        float rs0 = 0.f, rs1 = 0.f;
        #pragma unroll
        for (int ni = 0; ni < 8; ni++) {
            float p0 = exp2f((sf[ni][0] - mn0) * LOG2E);
            float p1 = exp2f((sf[ni][1] - mn0) * LOG2E);
            float p2 = exp2f((sf[ni][2] - mn1) * LOG2E);
            float p3 = exp2f((sf[ni][3] - mn1) * LOG2E);
            rs0 += p0 + p1;
            rs1 += p2 + p3;
            sf[ni][0] = p0; sf[ni][1] = p1; sf[ni][2] = p2; sf[ni][3] = p3;
            of[ni][0] *= a0; of[ni][1] *= a0; of[ni][2] *= a1; of[ni][3] *= a1;
        }
        rs0 += __shfl_xor_sync(0xffffffffu, rs0, 1);
        rs0 += __shfl_xor_sync(0xffffffffu, rs0, 2);
        rs1 += __shfl_xor_sync(0xffffffffu, rs1, 1);
        rs1 += __shfl_xor_sync(0xffffffffu, rs1, 2);
        l0 = l0 * a0 + rs0;
        l1 = l1 * a1 + rs1;
        m0 = mn0; m1 = mn1;

        __syncthreads();

        #pragma unroll
        for (int ni = 0; ni < 8; ni++) {
            int col = ni * 8 + 2 * t4;
            Ks[wm + g     ][col    ] = __uint_as_float(f2tf32(sf[ni][0]));
            Ks[wm + g     ][col + 1] = __uint_as_float(f2tf32(sf[ni][1]));
            Ks[wm + g + 8 ][col    ] = __uint_as_float(f2tf32(sf[ni][2]));
            Ks[wm + g + 8 ][col + 1] = __uint_as_float(f2tf32(sf[ni][3]));
        }
        __syncthreads();

        #pragma unroll
        for (int kk = 0; kk < 8; kk++) {
            uint32_t af0 = __float_as_uint(Ks[wm + g     ][kk * 8 + t4    ]);
            uint32_t af1 = __float_as_uint(Ks[wm + g + 8 ][kk * 8 + t4    ]);
            uint32_t af2 = __float_as_uint(Ks[wm + g     ][kk * 8 + t4 + 4]);
            uint32_t af3 = __float_as_uint(Ks[wm + g + 8 ][kk * 8 + t4 + 4]);
            #pragma unroll
            for (int ni = 0; ni < 8; ni++) {
                uint32_t b0 = __float_as_uint(Vs[kk * 8 + t4    ][ni * 8 + g]);
                uint32_t b1 = __float_as_uint(Vs[kk * 8 + t4 + 4][ni * 8 + g]);
                mma_tf32(of[ni][0], of[ni][1], of[ni][2], of[ni][3],
                         af0, af1, af2, af3, b0, b1);
            }
        }
        __syncthreads();
    }

    const float inv0 = 1.0f / l0;
    const float inv1 = 1.0f / l1;
    #pragma unroll
    for (int ni = 0; ni < 8; ni++) {
        int col = h * DH + ni * 8 + 2 * t4;
        int r0 = q0 + wm + g;
        *(float2*)(ctx + (size_t)r0 * HIDDEN + col) =
            make_float2(__uint_as_float(f2tf32(of[ni][0] * inv0)),
                        __uint_as_float(f2tf32(of[ni][1] * inv0)));
        *(float2*)(ctx + (size_t)(r0 + 8) * HIDDEN + col) =
            make_float2(__uint_as_float(f2tf32(of[ni][2] * inv1)),
                        __uint_as_float(f2tf32(of[ni][3] * inv1)));
    }
}

// ---------------------------------------------------------------------------
extern "C" void kernel_launch(void* const* d_in, const int* in_sizes, int n_in,
                              void* d_out, int out_size)
{
    (void)in_sizes; (void)n_in; (void)out_size;
    const float* x  = (const float*)d_in[0];
    const int*   cu = (const int*)d_in[1];
    const float* Wq = (const float*)d_in[2];
    const float* bq = (const float*)d_in[3];
    const float* Wk = (const float*)d_in[4];
    const float* bk = (const float*)d_in[5];
    const float* Wv = (const float*)d_in[6];
    const float* bv = (const float*)d_in[7];
    const float* Wo = (const float*)d_in[8];
    const float* bo = (const float*)d_in[9];
    float* out = (float*)d_out;

    float *q, *k, *v, *ctx, *xt, *wq, *wk, *wv, *wo;
    cudaGetSymbolAddress((void**)&q,   g_q);
    cudaGetSymbolAddress((void**)&k,   g_k);
    cudaGetSymbolAddress((void**)&v,   g_v);
    cudaGetSymbolAddress((void**)&ctx, g_ctx);
    cudaGetSymbolAddress((void**)&xt,  g_xt);
    cudaGetSymbolAddress((void**)&wq,  g_wq);
    cudaGetSymbolAddress((void**)&wk,  g_wk);
    cudaGetSymbolAddress((void**)&wv,  g_wv);
    cudaGetSymbolAddress((void**)&wo,  g_wo);

    // Round inputs to tf32 once (x: 2M elems needs 2048 blocks of 256*4)
    round_tf32_kernel<<<dim3(2048, 1, 5), 256>>>(x, Wq, Wk, Wv, Wo,
                                                 xt, wq, wk, wv, wo);

    // Fused QKV projections (z selects the weight/bias/output triple)
    dim3 qkvGrid(HIDDEN / 128, TOTAL / 128, 3);
    gemm3_tf32_nt_bias<<<qkvGrid, 256>>>(xt,
                                         wq, bq, q,
                                         wk, bk, k,
                                         wv, bv, v,
                                         TOTAL, HIDDEN, HIDDEN);

    flash_attn_kernel<<<dim3(TOTAL / 64, NHEAD), 128>>>(q, k, v, cu, ctx);

    // Output projection (single z slice; ctx already tf32-rounded)
    dim3 oGrid(HIDDEN / 128, TOTAL / 128, 1);
    gemm3_tf32_nt_bias<<<oGrid, 256>>>(ctx,
                                       wo, bo, out,
                                       wo, bo, out,
                                       wo, bo, out,
                                       TOTAL, HIDDEN, HIDDEN);
}